// round 2
// baseline (speedup 1.0000x reference)
#include <cuda_runtime.h>
#include <cstdint>

#define BB 128
#define TT 1024
#define DD 64
#define HH 256
#define OO 128
#define THREADS 256

typedef unsigned long long ull;

// smem float offsets
#define OFF_WX1 0        // [64][64]  k-major: [k*64 + j]
#define OFF_WH1 4096     // [256][64]
#define OFF_WX2 20480    // [256][64]
#define OFF_WH2 36864    // [256][64]
#define OFF_H1  53248    // [2][1024]  h1[p][k*4+m]
#define OFF_H2  55296    // [2][1024]
#define OFF_XT  57344    // [256]      xT[k*4+m]
#define OFF_SCR 57600    // [512] floats = 128 float4, scr4[q*32+jloc]
#define SMEM_FLOATS 58112
#define SMEM_BYTES (SMEM_FLOATS * 4)  // 232448 = 227KB max opt-in

__device__ __forceinline__ ull ffma2(ull a, ull b, ull c) {
    ull d;
    asm("fma.rn.f32x2 %0,%1,%2,%3;" : "=l"(d) : "l"(a), "l"(b), "l"(c));
    return d;
}
__device__ __forceinline__ ull addf2(ull a, ull b) {
    ull d;
    asm("add.rn.f32x2 %0,%1,%2;" : "=l"(d) : "l"(a), "l"(b));
    return d;
}
__device__ __forceinline__ ull pk2(float lo, float hi) {
    ull d;
    asm("mov.b64 %0,{%1,%2};" : "=l"(d) : "f"(lo), "f"(hi));
    return d;
}
__device__ __forceinline__ void up2(ull a, float& lo, float& hi) {
    asm("mov.b64 {%0,%1},%2;" : "=f"(lo), "=f"(hi) : "l"(a));
}
__device__ __forceinline__ void cbar() {
    asm volatile("barrier.cluster.arrive.aligned;" ::: "memory");
    asm volatile("barrier.cluster.wait.aligned;" ::: "memory");
}
__device__ __forceinline__ uint32_t s2u(const void* p) {
    uint32_t a;
    asm("{.reg .u64 t; cvta.to.shared.u64 t, %1; cvt.u32.u64 %0, t;}" : "=r"(a) : "l"(p));
    return a;
}

// Accumulate N k-steps: w points at &W[k0*64 + j] (stride 64 floats per k),
// hv points at float4 rows [k][m0..m3]. Two accumulator sets for ILP.
template <int N>
__device__ __forceinline__ void accum(const float* __restrict__ w,
                                      const float4* __restrict__ hv,
                                      ull& a01, ull& a23, ull& c01, ull& c23) {
#pragma unroll
    for (int i = 0; i < N; i += 2) {
        float w0 = w[i * 64];
        float4 v0 = hv[i];
        ull wp0 = pk2(w0, w0);
        a01 = ffma2(wp0, pk2(v0.x, v0.y), a01);
        a23 = ffma2(wp0, pk2(v0.z, v0.w), a23);
        float w1 = w[(i + 1) * 64];
        float4 v1 = hv[i + 1];
        ull wp1 = pk2(w1, w1);
        c01 = ffma2(wp1, pk2(v1.x, v1.y), c01);
        c23 = ffma2(wp1, pk2(v1.z, v1.w), c23);
    }
}

// Two-wave reduction over q + tanh + DSMEM broadcast of this CTA's 64 columns
// into dst buffer of all 4 cluster CTAs. dst_u32: byte smem addr of dst buffer.
__device__ __forceinline__ void reduce_bcast(float* sm, int tid, int j, int q,
                                             ull a01, ull a23, ull c01, ull c23,
                                             float biasA, float biasB,
                                             uint32_t dst_u32, int colg) {
    ull s01 = addf2(a01, c01), s23 = addf2(a23, c23);
    float4 part;
    up2(s01, part.x, part.y);
    up2(s23, part.z, part.w);
    float4* scr4 = (float4*)(sm + OFF_SCR);
    int jloc = j & 31, wj = j >> 5;
    int jj = tid >> 2, m = tid & 3;

    // ---- wave 0: columns j = 0..31 ----
    __syncthreads();                      // scratch free (prev use done)
    if (wj == 0) scr4[q * 32 + jloc] = part;   // conflict-free STS.128
    __syncthreads();
    if (tid < 128) {
        float s = sm[OFF_SCR + 0 + jj * 4 + m] + sm[OFF_SCR + 128 + jj * 4 + m]
                + sm[OFF_SCR + 256 + jj * 4 + m] + sm[OFF_SCR + 384 + jj * 4 + m];
        float h = tanhf(s + biasA);
        uint32_t lo = dst_u32 + (((colg + jj) << 2) + m) * 4u;
#pragma unroll
        for (int r = 0; r < 4; r++) {
            uint32_t ra;
            asm volatile("mapa.shared::cluster.u32 %0,%1,%2;" : "=r"(ra) : "r"(lo), "r"(r));
            asm volatile("st.shared::cluster.f32 [%0],%1;" :: "r"(ra), "f"(h) : "memory");
        }
    }
    // ---- wave 1: columns j = 32..63 ----
    __syncthreads();
    if (wj == 1) scr4[q * 32 + jloc] = part;
    __syncthreads();
    if (tid < 128) {
        float s = sm[OFF_SCR + 0 + jj * 4 + m] + sm[OFF_SCR + 128 + jj * 4 + m]
                + sm[OFF_SCR + 256 + jj * 4 + m] + sm[OFF_SCR + 384 + jj * 4 + m];
        float h = tanhf(s + biasB);
        uint32_t lo = dst_u32 + (((colg + 32 + jj) << 2) + m) * 4u;
#pragma unroll
        for (int r = 0; r < 4; r++) {
            uint32_t ra;
            asm volatile("mapa.shared::cluster.u32 %0,%1,%2;" : "=r"(ra) : "r"(lo), "r"(r));
            asm volatile("st.shared::cluster.f32 [%0],%1;" :: "r"(ra), "f"(h) : "memory");
        }
    }
}

__global__ void __launch_bounds__(THREADS, 1) __cluster_dims__(4, 1, 1)
rnn_kernel(const float* __restrict__ x, const float* __restrict__ Wx1,
           const float* __restrict__ Wh1, const float* __restrict__ b1,
           const float* __restrict__ Wx2, const float* __restrict__ Wh2,
           const float* __restrict__ b2, const float* __restrict__ Wd,
           const float* __restrict__ bd, float* __restrict__ out) {
    extern __shared__ float sm[];
    int tid = threadIdx.x;
    int j = tid & 63, q = tid >> 6;
    uint32_t rank;
    asm("mov.u32 %0, %%cluster_ctarank;" : "=r"(rank));
    int cid = (int)blockIdx.x >> 2;
    int bm0 = cid * 4;           // first global batch row of this cluster
    int colg = (int)rank * 64;   // first h-column owned by this CTA

    // ---- load weight slices (k-major, stride 64) ----
    for (int i = tid; i < 64 * 64; i += THREADS) {
        int k = i >> 6, jj = i & 63;
        sm[OFF_WX1 + i] = Wx1[k * HH + colg + jj];
    }
    for (int i = tid; i < 256 * 64; i += THREADS) {
        int k = i >> 6, jj = i & 63;
        sm[OFF_WH1 + i] = Wh1[k * HH + colg + jj];
        sm[OFF_WX2 + i] = Wx2[k * HH + colg + jj];
        sm[OFF_WH2 + i] = Wh2[k * HH + colg + jj];
    }
    for (int i = tid; i < 2048; i += THREADS) {
        sm[OFF_H1 + i] = 0.f;
        sm[OFF_H2 + i] = 0.f;
    }
    float b1A = 0.f, b1B = 0.f, b2A = 0.f, b2B = 0.f;
    if (tid < 128) {
        int jj = tid >> 2;
        b1A = b1[colg + jj];
        b1B = b1[colg + 32 + jj];
        b2A = b2[colg + jj];
        b2B = b2[colg + 32 + jj];
    }
    uint32_t su = s2u(sm);
    __syncthreads();
    cbar();  // all cluster CTAs initialized before any DSMEM broadcast

    const float* wx1 = sm + OFF_WX1 + q * 16 * 64 + j;
    const float* wh1 = sm + OFF_WH1 + q * 64 * 64 + j;
    const float* wx2 = sm + OFF_WX2 + q * 64 * 64 + j;
    const float* wh2 = sm + OFF_WH2 + q * 64 * 64 + j;
    const float4* xt4 = (const float4*)(sm + OFF_XT) + q * 16;
    const size_t xrow = (size_t)(bm0 + (tid & 3)) * (TT * DD) + (tid >> 2);

#pragma unroll 1
    for (int t = 0; t < TT; t++) {
        int p = t & 1, pn = p ^ 1;
        // stage x_t transposed: xT[k*4+m]
        sm[OFF_XT + tid] = x[xrow + (size_t)t * DD];
        __syncthreads();

        // layer 1: h1 = tanh(x_t Wx1 + h1 Wh1 + b1)
        ull a01 = 0, a23 = 0, c01 = 0, c23 = 0;
        accum<16>(wx1, xt4, a01, a23, c01, c23);
        accum<64>(wh1, (const float4*)(sm + OFF_H1 + pn * 1024) + q * 64, a01, a23, c01, c23);
        reduce_bcast(sm, tid, j, q, a01, a23, c01, c23, b1A, b1B,
                     su + (OFF_H1 + p * 1024) * 4u, colg);
        cbar();

        // layer 2: h2 = tanh(h1 Wx2 + h2 Wh2 + b2)
        a01 = 0; a23 = 0; c01 = 0; c23 = 0;
        accum<64>(wx2, (const float4*)(sm + OFF_H1 + p * 1024) + q * 64, a01, a23, c01, c23);
        accum<64>(wh2, (const float4*)(sm + OFF_H2 + pn * 1024) + q * 64, a01, a23, c01, c23);
        reduce_bcast(sm, tid, j, q, a01, a23, c01, c23, b2A, b2B,
                     su + (OFF_H2 + p * 1024) * 4u, colg);
        cbar();
    }

    // ---- epilogue: rank 0 computes dense + softmax for its 4 rows ----
    if (rank == 0) {
        const float* h2f = sm + OFF_H2 + ((TT - 1) & 1) * 1024;  // [k*4+m]
        int m = tid >> 6, o0 = tid & 63;
        float l0 = bd[o0], l1 = bd[o0 + 64];
#pragma unroll 4
        for (int k = 0; k < HH; k++) {
            float h = h2f[k * 4 + m];
            l0 += h * Wd[k * OO + o0];
            l1 += h * Wd[k * OO + o0 + 64];
        }
        sm[OFF_SCR + m * 128 + o0] = l0;
        sm[OFF_SCR + m * 128 + o0 + 64] = l1;
        __syncthreads();
        if (tid < 128) {
            int mm = tid >> 5, lane = tid & 31;
            const float* L = sm + OFF_SCR + mm * 128;
            float v0 = L[lane], v1 = L[lane + 32], v2 = L[lane + 64], v3 = L[lane + 96];
            float mx = fmaxf(fmaxf(v0, v1), fmaxf(v2, v3));
#pragma unroll
            for (int s = 16; s; s >>= 1) mx = fmaxf(mx, __shfl_xor_sync(0xffffffffu, mx, s));
            float e0 = __expf(v0 - mx), e1 = __expf(v1 - mx);
            float e2 = __expf(v2 - mx), e3 = __expf(v3 - mx);
            float ssum = e0 + e1 + e2 + e3;
#pragma unroll
            for (int s = 16; s; s >>= 1) ssum += __shfl_xor_sync(0xffffffffu, ssum, s);
            float inv = 1.f / ssum;
            float* orow = out + (size_t)(bm0 + mm) * OO;
            orow[lane] = e0 * inv;
            orow[lane + 32] = e1 * inv;
            orow[lane + 64] = e2 * inv;
            orow[lane + 96] = e3 * inv;
        }
    }
}

extern "C" void kernel_launch(void* const* d_in, const int* in_sizes, int n_in,
                              void* d_out, int out_size) {
    cudaFuncSetAttribute(rnn_kernel, cudaFuncAttributeMaxDynamicSharedMemorySize, SMEM_BYTES);
    rnn_kernel<<<128, THREADS, SMEM_BYTES>>>(
        (const float*)d_in[0], (const float*)d_in[1], (const float*)d_in[2],
        (const float*)d_in[3], (const float*)d_in[4], (const float*)d_in[5],
        (const float*)d_in[6], (const float*)d_in[7], (const float*)d_in[8],
        (float*)d_out);
}

// round 3
// speedup vs baseline: 1.0729x; 1.0729x over previous
#include <cuda_runtime.h>
#include <cstdint>

#define TT 1024
#define DD 64
#define HH 256
#define OO 128
#define THREADS 256

typedef unsigned long long ull;

// smem float offsets (static 43 KB)
#define OFF_WX1 0       // [64][64]  wx1s[k*64 + jloc]
#define OFF_H1  4096    // [2][1024] h1[p][kcol*4 + m]
#define OFF_H2  6144    // [2][1024]
#define OFF_XT  8192    // [2][256]  xT[p][k*4 + m]
#define OFF_SCR 8704    // [8][264]  padded reduction scratch
#define SMEM_FLOATS 10816

__device__ __forceinline__ ull ffma2(ull a, ull b, ull c) {
    ull d; asm("fma.rn.f32x2 %0,%1,%2,%3;" : "=l"(d) : "l"(a), "l"(b), "l"(c)); return d;
}
__device__ __forceinline__ ull pk2(float lo, float hi) {
    ull d; asm("mov.b64 %0,{%1,%2};" : "=l"(d) : "f"(lo), "f"(hi)); return d;
}
__device__ __forceinline__ void up2(ull a, float& lo, float& hi) {
    asm("mov.b64 {%0,%1},%2;" : "=f"(lo), "=f"(hi) : "l"(a));
}
__device__ __forceinline__ uint32_t s2u(const void* p) {
    uint32_t a;
    asm("{.reg .u64 t; cvta.to.shared.u64 t, %1; cvt.u32.u64 %0, t;}" : "=r"(a) : "l"(p));
    return a;
}
#define CARRIVE() asm volatile("barrier.cluster.arrive.aligned;" ::: "memory")
#define CWAIT()   asm volatile("barrier.cluster.wait.aligned;" ::: "memory")

// 32 k-steps against register-resident weight pair arrays.
// hv: float4 rows h[k][m0..3] (broadcast LDS.128). Accumulators packed over m.
__device__ __forceinline__ void accum_reg(const float (&wA)[32], const float (&wB)[32],
                                          const float4* __restrict__ hv,
                                          ull& aA01, ull& aA23, ull& aB01, ull& aB23) {
#pragma unroll
    for (int i = 0; i < 32; i++) {
        float4 h4 = hv[i];
        ull H01 = pk2(h4.x, h4.y), H23 = pk2(h4.z, h4.w);
        ull wdA = pk2(wA[i], wA[i]);
        ull wdB = pk2(wB[i], wB[i]);
        aA01 = ffma2(wdA, H01, aA01);
        aA23 = ffma2(wdA, H23, aA23);
        aB01 = ffma2(wdB, H01, aB01);
        aB23 = ffma2(wdB, H23, aB23);
    }
}

// 8 k-steps of the x-projection, weights from smem (Wx1 slice).
__device__ __forceinline__ void accum_x(const float* __restrict__ smw, int q, int j2,
                                        const float4* __restrict__ xv,
                                        ull& aA01, ull& aA23, ull& aB01, ull& aB23) {
#pragma unroll
    for (int i = 0; i < 8; i++) {
        int k = 8 * q + i;
        float2 w = *(const float2*)(smw + k * 64 + 2 * j2);
        float4 h4 = xv[i];
        ull H01 = pk2(h4.x, h4.y), H23 = pk2(h4.z, h4.w);
        ull wdA = pk2(w.x, w.x);
        ull wdB = pk2(w.y, w.y);
        aA01 = ffma2(wdA, H01, aA01);
        aA23 = ffma2(wdA, H23, aA23);
        aB01 = ffma2(wdB, H01, aB01);
        aB23 = ffma2(wdB, H23, aB23);
    }
}

// 8-way reduce + bias + tanh + DSMEM broadcast to all 4 cluster CTAs.
__device__ __forceinline__ void reduce_bcast(float* sm, uint32_t su, int tid, int q, int j2,
                                             ull aA01, ull aA23, ull aB01, ull aB23,
                                             float bias, int dst_off, int colg) {
    __syncthreads();                      // prior scratch use complete
    float4 pA, pB;
    up2(aA01, pA.x, pA.y); up2(aA23, pA.z, pA.w);
    up2(aB01, pB.x, pB.y); up2(aB23, pB.z, pB.w);
    float* base = sm + OFF_SCR + q * 264 + 8 * j2;
    ((float4*)base)[0] = pA;              // thread covers outs [8*j2, 8*j2+8) densely
    ((float4*)base)[1] = pB;
    __syncthreads();
    float s = bias;
#pragma unroll
    for (int qq = 0; qq < 8; qq++) s += sm[OFF_SCR + qq * 264 + tid];
    float h = tanhf(s);
    uint32_t lo = su + (uint32_t)(dst_off + colg * 4 + tid) * 4u;
#pragma unroll
    for (int r = 0; r < 4; r++) {
        uint32_t ra;
        asm volatile("mapa.shared::cluster.u32 %0,%1,%2;" : "=r"(ra) : "r"(lo), "r"(r));
        asm volatile("st.shared::cluster.f32 [%0],%1;" :: "r"(ra), "f"(h) : "memory");
    }
}

__global__ void __launch_bounds__(THREADS, 1) __cluster_dims__(4, 1, 1)
rnn_kernel(const float* __restrict__ x, const float* __restrict__ Wx1,
           const float* __restrict__ Wh1, const float* __restrict__ b1,
           const float* __restrict__ Wx2, const float* __restrict__ Wh2,
           const float* __restrict__ b2, const float* __restrict__ Wd,
           const float* __restrict__ bd, float* __restrict__ out) {
    __shared__ __align__(16) float sm[SMEM_FLOATS];
    int tid = threadIdx.x;
    int q = tid >> 5, j2 = tid & 31;
    uint32_t rank;
    asm("mov.u32 %0, %%cluster_ctarank;" : "=r"(rank));
    int colg = (int)rank * 64;
    int bm0 = ((int)blockIdx.x >> 2) * 4;

    // Wx1 slice -> smem
    for (int i = tid; i < 4096; i += THREADS) {
        int k = i >> 6, jl = i & 63;
        sm[OFF_WX1 + i] = Wx1[k * HH + colg + jl];
    }
    // zero h1/h2/xT region (contiguous 4096..8704)
    for (int i = tid; i < 4608; i += THREADS) sm[OFF_H1 + i] = 0.f;

    // recurrent + layer-2 weights -> registers (pairs over j)
    float wh1A[32], wh1B[32], wx2A[32], wx2B[32], wh2A[32], wh2B[32];
    {
        const float2* g1 = (const float2*)Wh1;
        const float2* g2 = (const float2*)Wx2;
        const float2* g3 = (const float2*)Wh2;
        int cw = (colg >> 1) + j2;
#pragma unroll
        for (int i = 0; i < 32; i++) {
            float2 a = g1[(32 * q + i) * (HH / 2) + cw]; wh1A[i] = a.x; wh1B[i] = a.y;
            float2 b = g2[(32 * q + i) * (HH / 2) + cw]; wx2A[i] = b.x; wx2B[i] = b.y;
            float2 c = g3[(32 * q + i) * (HH / 2) + cw]; wh2A[i] = c.x; wh2B[i] = c.y;
        }
    }
    float b1v = b1[colg + (tid >> 2)];
    float b2v = b2[colg + (tid >> 2)];
    uint32_t su = s2u(sm);

    // stage x(0) transposed: xT[0][k*4+m]
    const size_t xbase = (size_t)(bm0 + (tid & 3)) * TT * DD + (tid >> 2);
    sm[OFF_XT + tid] = x[xbase];
    __syncthreads();
    CARRIVE(); CWAIT();   // cluster ready before any DSMEM traffic

    // initial L1 partials for t=0 (h1(-1)=0 buffer is parity 1)
    ull aA01 = 0, aA23 = 0, aB01 = 0, aB23 = 0;
    accum_x(sm + OFF_WX1, q, j2, (const float4*)(sm + OFF_XT) + 8 * q, aA01, aA23, aB01, aB23);
    accum_reg(wh1A, wh1B, (const float4*)(sm + OFF_H1 + 1024) + 32 * q, aA01, aA23, aB01, aB23);

#pragma unroll 1
    for (int t = 0; t < TT; t++) {
        int p = t & 1, pn = p ^ 1;

        // ---- Phase A: finish layer 1, broadcast h1(t) ----
        reduce_bcast(sm, su, tid, q, j2, aA01, aA23, aB01, aB23, b1v, OFF_H1 + p * 1024, colg);
        CARRIVE();                                    // barrier #1 (h1(t) published)
        // barrier-hidden work: Wh2 * h2(t-1)
        aA01 = 0; aA23 = 0; aB01 = 0; aB23 = 0;
        accum_reg(wh2A, wh2B, (const float4*)(sm + OFF_H2 + pn * 1024) + 32 * q,
                  aA01, aA23, aB01, aB23);
        if (t + 1 < TT) sm[OFF_XT + pn * 256 + tid] = x[xbase + (size_t)(t + 1) * DD];
        CWAIT();                                      // h1(t) complete everywhere

        // ---- Phase B: Wx2 * h1(t), finish layer 2, broadcast h2(t) ----
        accum_reg(wx2A, wx2B, (const float4*)(sm + OFF_H1 + p * 1024) + 32 * q,
                  aA01, aA23, aB01, aB23);
        reduce_bcast(sm, su, tid, q, j2, aA01, aA23, aB01, aB23, b2v, OFF_H2 + p * 1024, colg);
        CARRIVE();                                    // barrier #2 (h2(t) published)
        // barrier-hidden work: all of L1(t+1) (x(t+1) staged, h1(t) valid)
        aA01 = 0; aA23 = 0; aB01 = 0; aB23 = 0;
        if (t + 1 < TT) {
            accum_x(sm + OFF_WX1, q, j2, (const float4*)(sm + OFF_XT + pn * 256) + 8 * q,
                    aA01, aA23, aB01, aB23);
            accum_reg(wh1A, wh1B, (const float4*)(sm + OFF_H1 + p * 1024) + 32 * q,
                      aA01, aA23, aB01, aB23);
        }
        CWAIT();
    }

    __syncthreads();   // scratch free for epilogue

    // ---- epilogue: rank 0 does dense + softmax for its 4 rows ----
    if (rank == 0) {
        const float* h2f = sm + OFF_H2 + 1024;   // parity of t=1023 is 1
        int m = tid >> 6, o0 = tid & 63;
        float l0 = bd[o0], l1 = bd[o0 + 64];
#pragma unroll 4
        for (int k = 0; k < HH; k++) {
            float h = h2f[k * 4 + m];
            l0 += h * Wd[k * OO + o0];
            l1 += h * Wd[k * OO + o0 + 64];
        }
        sm[OFF_SCR + m * 128 + o0] = l0;
        sm[OFF_SCR + m * 128 + o0 + 64] = l1;
        __syncthreads();
        if (tid < 128) {
            int mm = tid >> 5, lane = tid & 31;
            const float* L = sm + OFF_SCR + mm * 128;
            float v0 = L[lane], v1 = L[lane + 32], v2 = L[lane + 64], v3 = L[lane + 96];
            float mx = fmaxf(fmaxf(v0, v1), fmaxf(v2, v3));
#pragma unroll
            for (int s = 16; s; s >>= 1) mx = fmaxf(mx, __shfl_xor_sync(0xffffffffu, mx, s));
            float e0 = __expf(v0 - mx), e1 = __expf(v1 - mx);
            float e2 = __expf(v2 - mx), e3 = __expf(v3 - mx);
            float ssum = e0 + e1 + e2 + e3;
#pragma unroll
            for (int s = 16; s; s >>= 1) ssum += __shfl_xor_sync(0xffffffffu, ssum, s);
            float inv = 1.f / ssum;
            float* orow = out + (size_t)(bm0 + mm) * OO;
            orow[lane] = e0 * inv;
            orow[lane + 32] = e1 * inv;
            orow[lane + 64] = e2 * inv;
            orow[lane + 96] = e3 * inv;
        }
    }
}

extern "C" void kernel_launch(void* const* d_in, const int* in_sizes, int n_in,
                              void* d_out, int out_size) {
    rnn_kernel<<<128, THREADS>>>(
        (const float*)d_in[0], (const float*)d_in[1], (const float*)d_in[2],
        (const float*)d_in[3], (const float*)d_in[4], (const float*)d_in[5],
        (const float*)d_in[6], (const float*)d_in[7], (const float*)d_in[8],
        (float*)d_out);
}

// round 5
// speedup vs baseline: 2.0745x; 1.9335x over previous
#include <cuda_runtime.h>
#include <cstdint>

#define TT 1024
#define DD 64
#define HH 256
#define OO 128
#define THREADS 512

typedef unsigned long long ull;

// smem float offsets (dynamic, 51728 B)
#define OFF_WX1 0        // [64][64]   wx1[k*64 + jloc]
#define OFF_H1  4096     // [2][1024]  h1[p][col*4 + m]
#define OFF_H2  6144     // [2][1024]
#define OFF_XT  8192     // [2][256]   xT[p][k*4 + m]
#define OFF_SCR 8704     // [16][256]  reduction scratch
#define OFF_MBAR 12928   // 2 x u64 mbarriers
#define SMEM_FLOATS 12932
#define SMEM_BYTES (SMEM_FLOATS * 4)
#define MBAR1_B (OFF_MBAR * 4)
#define MBAR2_B (OFF_MBAR * 4 + 8)

__device__ __forceinline__ ull ffma2(ull a, ull b, ull c) {
    ull d; asm("fma.rn.f32x2 %0,%1,%2,%3;" : "=l"(d) : "l"(a), "l"(b), "l"(c)); return d;
}
__device__ __forceinline__ ull pk2(float lo, float hi) {
    ull d; asm("mov.b64 %0,{%1,%2};" : "=l"(d) : "f"(lo), "f"(hi)); return d;
}
__device__ __forceinline__ void up2(ull a, float& lo, float& hi) {
    asm("mov.b64 {%0,%1},%2;" : "=f"(lo), "=f"(hi) : "l"(a));
}
__device__ __forceinline__ uint32_t s2u(const void* p) {
    uint32_t a;
    asm("{.reg .u64 t; cvta.to.shared.u64 t, %1; cvt.u32.u64 %0, t;}" : "=r"(a) : "l"(p));
    return a;
}
__device__ __forceinline__ void mbar_init(uint32_t m, uint32_t cnt) {
    asm volatile("mbarrier.init.shared.b64 [%0], %1;" :: "r"(m), "r"(cnt) : "memory");
}
__device__ __forceinline__ void mbar_expect(uint32_t m, uint32_t bytes) {
    asm volatile("mbarrier.arrive.expect_tx.shared.b64 _, [%0], %1;" :: "r"(m), "r"(bytes) : "memory");
}
__device__ __forceinline__ void mbar_wait(uint32_t m, uint32_t parity) {
    asm volatile(
        "{\n\t.reg .pred P;\n"
        "W%=:\n\t"
        "mbarrier.try_wait.parity.acquire.cta.shared::cta.b64 P, [%0], %1, 0x989680;\n\t"
        "@!P bra W%=;\n\t}"
        :: "r"(m), "r"(parity) : "memory");
}
__device__ __forceinline__ void st_async_f32(uint32_t daddr, float v, uint32_t dmbar) {
    asm volatile("st.async.shared::cluster.mbarrier::complete_tx::bytes.f32 [%0], %1, [%2];"
                 :: "r"(daddr), "f"(v), "r"(dmbar) : "memory");
}
#define CLUSTER_SYNC() do { \
    asm volatile("barrier.cluster.arrive.aligned;" ::: "memory"); \
    asm volatile("barrier.cluster.wait.aligned;" ::: "memory"); } while (0)

// 16 k-steps vs register weights; hv = broadcast float4 rows h[k][m0..3]
__device__ __forceinline__ void accum16(const float (&wA)[16], const float (&wB)[16],
                                        const float4* __restrict__ hv,
                                        ull& aA01, ull& aA23, ull& aB01, ull& aB23) {
#pragma unroll
    for (int i = 0; i < 16; i++) {
        float4 h4 = hv[i];
        ull H01 = pk2(h4.x, h4.y), H23 = pk2(h4.z, h4.w);
        ull wdA = pk2(wA[i], wA[i]);
        ull wdB = pk2(wB[i], wB[i]);
        aA01 = ffma2(wdA, H01, aA01);
        aA23 = ffma2(wdA, H23, aA23);
        aB01 = ffma2(wdB, H01, aB01);
        aB23 = ffma2(wdB, H23, aB23);
    }
}

// 4 k-steps of x-projection (Wx1 slice from smem), warp w covers k in [4w,4w+4).
// xv must already point at this warp's k-slice (rows 4w..4w+3).
__device__ __forceinline__ void accum_x(const float* __restrict__ smw, int w, int lane,
                                        const float4* __restrict__ xv,
                                        ull& aA01, ull& aA23, ull& aB01, ull& aB23) {
#pragma unroll
    for (int i = 0; i < 4; i++) {
        float2 wv = *(const float2*)(smw + (4 * w + i) * 64 + 2 * lane);
        float4 h4 = xv[i];
        ull H01 = pk2(h4.x, h4.y), H23 = pk2(h4.z, h4.w);
        ull wdA = pk2(wv.x, wv.x);
        ull wdB = pk2(wv.y, wv.y);
        aA01 = ffma2(wdA, H01, aA01);
        aA23 = ffma2(wdA, H23, aA23);
        aB01 = ffma2(wdB, H01, aB01);
        aB23 = ffma2(wdB, H23, aB23);
    }
}

// 16-way reduce + bias + tanh + st.async broadcast to all 4 cluster CTAs.
__device__ __forceinline__ void reduce_bcast(float* sm, int tid, int w, int lane,
                                             ull aA01, ull aA23, ull aB01, ull aB23,
                                             float bias, int dst_off, int colg,
                                             const uint32_t (&peer)[4], uint32_t mbar_b) {
    __syncthreads();                           // prior scratch use complete
    float4 pA, pB;
    up2(aA01, pA.x, pA.y); up2(aA23, pA.z, pA.w);
    up2(aB01, pB.x, pB.y); up2(aB23, pB.z, pB.w);
    float4* base = (float4*)(sm + OFF_SCR + w * 256 + 8 * lane);
    base[0] = pA;                              // outs [8*lane, 8*lane+8) dense
    base[1] = pB;
    __syncthreads();
    if (tid < 256) {
        float s = bias;
#pragma unroll
        for (int qq = 0; qq < 16; qq++) s += sm[OFF_SCR + qq * 256 + tid];
        float h = tanhf(s);
        uint32_t off = (uint32_t)(dst_off + colg * 4 + tid) * 4u;
#pragma unroll
        for (int r = 0; r < 4; r++)
            st_async_f32(peer[r] + off, h, peer[r] + mbar_b);
    }
}

__global__ void __launch_bounds__(THREADS, 1) __cluster_dims__(4, 1, 1)
rnn_kernel(const float* __restrict__ x, const float* __restrict__ Wx1,
           const float* __restrict__ Wh1, const float* __restrict__ b1,
           const float* __restrict__ Wx2, const float* __restrict__ Wh2,
           const float* __restrict__ b2, const float* __restrict__ Wd,
           const float* __restrict__ bd, float* __restrict__ out) {
    extern __shared__ float sm[];
    int tid = threadIdx.x;
    int w = tid >> 5, lane = tid & 31;
    uint32_t rank;
    asm("mov.u32 %0, %%cluster_ctarank;" : "=r"(rank));
    int colg = (int)rank * 64;
    int bm0 = ((int)blockIdx.x >> 2) * 4;

    // Wx1 slice -> smem (k-major, 64 cols of this CTA)
    for (int i = tid; i < 4096; i += THREADS) {
        int k = i >> 6, jl = i & 63;
        sm[OFF_WX1 + i] = Wx1[k * HH + colg + jl];
    }
    // zero h buffers + xT
    for (int i = tid; i < 4608; i += THREADS) sm[OFF_H1 + i] = 0.f;

    // recurrent + layer-2 weights -> registers: warp w owns k in [16w,16w+16),
    // lane owns cols {colg+2*lane, colg+2*lane+1}
    float wh1A[16], wh1B[16], wx2A[16], wx2B[16], wh2A[16], wh2B[16];
    {
        const float2* g1 = (const float2*)Wh1;
        const float2* g2 = (const float2*)Wx2;
        const float2* g3 = (const float2*)Wh2;
        int cw = (colg >> 1) + lane;
#pragma unroll
        for (int i = 0; i < 16; i++) {
            float2 a = g1[(16 * w + i) * (HH / 2) + cw]; wh1A[i] = a.x; wh1B[i] = a.y;
            float2 b = g2[(16 * w + i) * (HH / 2) + cw]; wx2A[i] = b.x; wx2B[i] = b.y;
            float2 c = g3[(16 * w + i) * (HH / 2) + cw]; wh2A[i] = c.x; wh2B[i] = c.y;
        }
    }
    float b1v = 0.f, b2v = 0.f;
    if (tid < 256) {
        b1v = b1[colg + (tid >> 2)];
        b2v = b2[colg + (tid >> 2)];
    }
    uint32_t su = s2u(sm);
    uint32_t peer[4];
#pragma unroll
    for (int r = 0; r < 4; r++)
        asm("mapa.shared::cluster.u32 %0,%1,%2;" : "=r"(peer[r]) : "r"(su), "r"(r));

    if (tid == 0) {
        mbar_init(su + MBAR1_B, 1);
        mbar_init(su + MBAR2_B, 1);
    }
    // stage x(0): xT[0][k*4+m]
    const size_t xbase = (size_t)(bm0 + (tid & 3)) * TT * DD + (tid >> 2);
    if (tid < 256) sm[OFF_XT + tid] = x[xbase];
    __syncthreads();
    CLUSTER_SYNC();   // mbarriers + buffers live before any st.async

    // initial L1(0) partials (h1(-1) = zeros in parity-1 buffer)
    ull aA01 = 0, aA23 = 0, aB01 = 0, aB23 = 0;
    accum_x(sm + OFF_WX1, w, lane, (const float4*)(sm + OFF_XT) + 4 * w,
            aA01, aA23, aB01, aB23);
    accum16(wh1A, wh1B, (const float4*)(sm + OFF_H1 + 1024) + 16 * w, aA01, aA23, aB01, aB23);

#pragma unroll 1
    for (int t = 0; t < TT; t++) {
        int p = t & 1, pn = p ^ 1;
        if (tid == 0) {                 // post this step's tx expectations
            mbar_expect(su + MBAR1_B, 4096);
            mbar_expect(su + MBAR2_B, 4096);
        }
        // ---- phase A: finish layer 1, broadcast h1(t) ----
        reduce_bcast(sm, tid, w, lane, aA01, aA23, aB01, aB23, b1v,
                     OFF_H1 + p * 1024, colg, peer, MBAR1_B);
        // hidden: Wh2*h2(t-1) + x prefetch
        aA01 = 0; aA23 = 0; aB01 = 0; aB23 = 0;
        accum16(wh2A, wh2B, (const float4*)(sm + OFF_H2 + pn * 1024) + 16 * w,
                aA01, aA23, aB01, aB23);
        if (t + 1 < TT && tid < 256)
            sm[OFF_XT + pn * 256 + tid] = x[xbase + (size_t)(t + 1) * DD];
        mbar_wait(su + MBAR1_B, (uint32_t)p);   // h1(t) fully arrived

        // ---- phase B: Wx2*h1(t), finish layer 2, broadcast h2(t) ----
        accum16(wx2A, wx2B, (const float4*)(sm + OFF_H1 + p * 1024) + 16 * w,
                aA01, aA23, aB01, aB23);
        reduce_bcast(sm, tid, w, lane, aA01, aA23, aB01, aB23, b2v,
                     OFF_H2 + p * 1024, colg, peer, MBAR2_B);
        // hidden: L1(t+1) = Wx1*x(t+1) + Wh1*h1(t)
        aA01 = 0; aA23 = 0; aB01 = 0; aB23 = 0;
        if (t + 1 < TT) {
            accum_x(sm + OFF_WX1, w, lane, (const float4*)(sm + OFF_XT + pn * 256) + 4 * w,
                    aA01, aA23, aB01, aB23);
            accum16(wh1A, wh1B, (const float4*)(sm + OFF_H1 + p * 1024) + 16 * w,
                    aA01, aA23, aB01, aB23);
        }
        mbar_wait(su + MBAR2_B, (uint32_t)p);   // h2(t) fully arrived
    }
    __syncthreads();

    // ---- epilogue: every rank outputs its own batch row (h2 replicated) ----
    {
        const float* h2f = sm + OFF_H2 + 1024;  // parity of t=1023 is 1
        int kq = tid >> 7, o = tid & 127;
        float part = 0.f;
#pragma unroll 8
        for (int i = 0; i < 64; i++) {
            int k = kq * 64 + i;
            part += h2f[k * 4 + rank] * Wd[k * OO + o];
        }
        sm[OFF_SCR + kq * 128 + o] = part;
        __syncthreads();
        if (tid < 128) {
            float l = bd[tid] + sm[OFF_SCR + tid] + sm[OFF_SCR + 128 + tid]
                    + sm[OFF_SCR + 256 + tid] + sm[OFF_SCR + 384 + tid];
            sm[OFF_SCR + 512 + tid] = l;
        }
        __syncthreads();
        if (tid < 32) {
            const float* L = sm + OFF_SCR + 512;
            float v0 = L[tid], v1 = L[tid + 32], v2 = L[tid + 64], v3 = L[tid + 96];
            float mx = fmaxf(fmaxf(v0, v1), fmaxf(v2, v3));
#pragma unroll
            for (int s = 16; s; s >>= 1) mx = fmaxf(mx, __shfl_xor_sync(0xffffffffu, mx, s));
            float e0 = __expf(v0 - mx), e1 = __expf(v1 - mx);
            float e2 = __expf(v2 - mx), e3 = __expf(v3 - mx);
            float ssum = e0 + e1 + e2 + e3;
#pragma unroll
            for (int s = 16; s; s >>= 1) ssum += __shfl_xor_sync(0xffffffffu, ssum, s);
            float inv = 1.f / ssum;
            float* orow = out + (size_t)(bm0 + (int)rank) * OO;
            orow[tid] = e0 * inv;
            orow[tid + 32] = e1 * inv;
            orow[tid + 64] = e2 * inv;
            orow[tid + 96] = e3 * inv;
        }
    }
    CLUSTER_SYNC();   // keep cluster alive until all in-flight st.async land
}

extern "C" void kernel_launch(void* const* d_in, const int* in_sizes, int n_in,
                              void* d_out, int out_size) {
    cudaFuncSetAttribute(rnn_kernel, cudaFuncAttributeMaxDynamicSharedMemorySize, SMEM_BYTES);
    rnn_kernel<<<128, THREADS, SMEM_BYTES>>>(
        (const float*)d_in[0], (const float*)d_in[1], (const float*)d_in[2],
        (const float*)d_in[3], (const float*)d_in[4], (const float*)d_in[5],
        (const float*)d_in[6], (const float*)d_in[7], (const float*)d_in[8],
        (float*)d_out);
}